// round 11
// baseline (speedup 1.0000x reference)
#include <cuda_runtime.h>
#include <math.h>

// Problem constants
#define LN   6
#define HN   12
#define DN   64
#define CN   768
#define VN   32000
#define BN_  2
#define TN   1024
#define BT   2048          // B*T
#define FN   3072          // 4*C
#define QKVN 2304          // 3*C

// ---------------- scratch (device globals; no allocations allowed) ----------
__device__ float g_h   [BT * CN];                       // residual stream
__device__ float g_ain [BT * CN];                       // layernorm output (tf32-rounded)
__device__ float g_qkv [BT * QKVN];                     // fused q|k|v
__device__ float g_att [BT * CN];                       // attention output (tf32-rounded)
__device__ float g_ffn [BT * FN];                       // MLP hidden (tf32-rounded)
__device__ float g_wt  [CN * QKVN];                     // transposed qkv weights (tf32)
__device__ float g_woc [LN * CN * CN];                  // tf32 copies of weights
__device__ float g_w1c [LN * CN * FN];
__device__ float g_w2c [LN * FN * CN];
__device__ float g_whc [CN * VN];

__device__ __forceinline__ unsigned f2tf(float x) {
    unsigned u;
    asm("cvt.rna.tf32.f32 %0, %1;" : "=r"(u) : "f"(x));
    return u;
}
__device__ __forceinline__ float f2tf_f(float x) { return __uint_as_float(f2tf(x)); }

// ---------------- tf32 pre-conversion (vectorized) ---------------------------
__global__ void cvtf_kernel(const float4* __restrict__ src, float4* __restrict__ dst, int n4) {
    int i = blockIdx.x * 256 + threadIdx.x;
    if (i >= n4) return;
    float4 v = src[i];
    dst[i] = make_float4(f2tf_f(v.x), f2tf_f(v.y), f2tf_f(v.z), f2tf_f(v.w));
}

// ---------------- embedding -------------------------------------------------
__global__ void embed_kernel(const int* __restrict__ x, const float* __restrict__ tok,
                             const float* __restrict__ pos, float* __restrict__ out) {
    int idx = blockIdx.x * 256 + threadIdx.x;
    if (idx >= BT * CN) return;
    int bt = idx / CN, c = idx % CN;
    int t = bt % TN;
    out[idx] = tok[(size_t)x[bt] * CN + c] + pos[t * CN + c];
}

// ---------------- weight transpose: (H,C,D)x3 -> (C, 3*H*D), tf32-rounded ---
__global__ void transpose_qkv_kernel(const float* __restrict__ Wq, const float* __restrict__ Wk,
                                     const float* __restrict__ Wv, float* __restrict__ out) {
    int idx = blockIdx.x * 256 + threadIdx.x;
    const int per = HN * CN * DN;
    if (idx >= 3 * per) return;
    int which = idx / per, r = idx % per;
    int h = r / (CN * DN);
    int c = (r / DN) % CN;
    int d = r % DN;
    const float* W = (which == 0) ? Wq : (which == 1) ? Wk : Wv;
    out[c * QKVN + which * CN + h * DN + d] = f2tf_f(W[(size_t)(h * CN + c) * DN + d]);
}

// ---------------- layernorm (tf32-rounded output: it only feeds GEMM A) -----
__global__ void layernorm_kernel(const float* __restrict__ x, const float* __restrict__ g,
                                 const float* __restrict__ b, float* __restrict__ out) {
    int row = blockIdx.x;
    const float* xr = x + (size_t)row * CN;
    float* orow = out + (size_t)row * CN;
    int tid = threadIdx.x;
    __shared__ float sred[32];

    float s = 0.f;
    for (int c = tid; c < CN; c += 256) s += xr[c];
    #pragma unroll
    for (int o = 16; o; o >>= 1) s += __shfl_xor_sync(0xffffffffu, s, o);
    if ((tid & 31) == 0) sred[tid >> 5] = s;
    __syncthreads();
    if (tid < 32) {
        float v = (tid < 8) ? sred[tid] : 0.f;
        #pragma unroll
        for (int o = 4; o; o >>= 1) v += __shfl_xor_sync(0xffffffffu, v, o);
        if (tid == 0) sred[0] = v;
    }
    __syncthreads();
    float mean = sred[0] * (1.0f / CN);
    __syncthreads();

    float vs = 0.f;
    for (int c = tid; c < CN; c += 256) { float d = xr[c] - mean; vs += d * d; }
    #pragma unroll
    for (int o = 16; o; o >>= 1) vs += __shfl_xor_sync(0xffffffffu, vs, o);
    if ((tid & 31) == 0) sred[tid >> 5] = vs;
    __syncthreads();
    if (tid < 32) {
        float v = (tid < 8) ? sred[tid] : 0.f;
        #pragma unroll
        for (int o = 4; o; o >>= 1) v += __shfl_xor_sync(0xffffffffu, v, o);
        if (tid == 0) sred[0] = v;
    }
    __syncthreads();
    float inv = rsqrtf(sred[0] * (1.0f / CN) + 1e-5f);
    for (int c = tid; c < CN; c += 256)
        orow[c] = f2tf_f((xr[c] - mean) * inv * g[c] + b[c]);
}

// ---------------- TF32 tensor-core GEMM, cp.async 3-stage, KCH=32 -----------
// Inputs MUST be tf32-pre-rounded floats. C = A@B [+bias][relu->round][+res].
// M%128==0, N%128==0, K%32==0, K/32>=2. Dynamic smem 107520B.
#define AST 36    // 32 cols + pad: A-frag banks (4g+tg) -> conflict-free
#define BST 136   // 128 cols + pad: B-frag banks (8tg+g) -> conflict-free
#define KCH 32
#define ASTAGE (128 * AST)
#define BSTAGE (32 * BST)
#define TG_SMEM ((3 * ASTAGE + 3 * BSTAGE) * 4)

__global__ __launch_bounds__(256) void tgemm_kernel(
        const float* __restrict__ A, const float* __restrict__ Bm,
        float* __restrict__ Cm, const float* __restrict__ bias,
        const float* __restrict__ res, int M, int N, int K, int relu) {
    extern __shared__ float dsm[];
    float* Asm = dsm;                       // [3][ASTAGE]
    float* Bsm = dsm + 3 * ASTAGE;          // [3][BSTAGE]
    int tid = threadIdx.x;
    int wid = tid >> 5, lane = tid & 31;
    int g = lane >> 2, tg = lane & 3;
    int wm = (wid >> 2) * 64;      // 0 / 64
    int wn = (wid & 3) * 32;       // 0,32,64,96

    const float* Ap = A + (size_t)(blockIdx.y * 128) * K;
    const float* Bp = Bm + (size_t)blockIdx.x * 128;

    float acc[4][4][4];
    #pragma unroll
    for (int i = 0; i < 4; i++)
        #pragma unroll
        for (int j = 0; j < 4; j++)
            #pragma unroll
            for (int r = 0; r < 4; r++) acc[i][j][r] = 0.f;

    // cp.async mapping: A tile 128x32 (4 float4/thread), B tile 32x128 (4 float4/thread)
    int a_r = tid >> 3;             // 0..31 (+32p)
    int a_c = (tid & 7) * 4;        // 0..28
    int b_r = tid >> 5;             // 0..7  (+8p)
    int b_c = (tid & 31) * 4;       // 0..124

    unsigned abase = (unsigned)__cvta_generic_to_shared(Asm);
    unsigned bbase = (unsigned)__cvta_generic_to_shared(Bsm);

#define ISSUE_STAGE(KT, BUF) do {                                                          \
    unsigned ab_ = abase + (unsigned)(BUF) * (ASTAGE * 4);                                 \
    unsigned bb_ = bbase + (unsigned)(BUF) * (BSTAGE * 4);                                 \
    const float* ap_ = Ap + (KT) * KCH;                                                    \
    const float* bp_ = Bp + (size_t)((KT) * KCH) * N;                                      \
    _Pragma("unroll")                                                                      \
    for (int p = 0; p < 4; p++)                                                            \
        asm volatile("cp.async.cg.shared.global [%0], [%1], 16;" ::                        \
            "r"(ab_ + (unsigned)(((a_r + p * 32) * AST + a_c) * 4)),                       \
            "l"(ap_ + (size_t)(a_r + p * 32) * K + a_c));                                  \
    _Pragma("unroll")                                                                      \
    for (int p = 0; p < 4; p++)                                                            \
        asm volatile("cp.async.cg.shared.global [%0], [%1], 16;" ::                        \
            "r"(bb_ + (unsigned)(((b_r + p * 8) * BST + b_c) * 4)),                        \
            "l"(bp_ + (size_t)(b_r + p * 8) * N + b_c));                                   \
    asm volatile("cp.async.commit_group;");                                                \
} while (0)

    int NT = K / KCH;               // >= 2 for all call sites (K=768 or 3072)
    ISSUE_STAGE(0, 0);
    ISSUE_STAGE(1, 1);

    int buf = 0;
    for (int kt = 0; kt < NT; kt++) {
        if (kt + 1 < NT) {
            asm volatile("cp.async.wait_group 1;");   // stage kt resident
        } else {
            asm volatile("cp.async.wait_group 0;");
        }
        __syncthreads();   // data visible to all; all warps done reading buf of kt-1

        if (kt + 2 < NT) {
            int nbuf = buf + 2; if (nbuf >= 3) nbuf -= 3;   // == (kt-1)%3, freed by sync
            ISSUE_STAGE(kt + 2, nbuf);
        }

        const unsigned* as = (const unsigned*)(Asm + buf * ASTAGE);
        const unsigned* bs = (const unsigned*)(Bsm + buf * BSTAGE);
        #pragma unroll
        for (int kk = 0; kk < KCH; kk += 8) {
            unsigned af[4][4], bf[4][2];
            #pragma unroll
            for (int i = 0; i < 4; i++) {
                int r = wm + i * 16 + g;
                af[i][0] = as[r * AST + kk + tg];
                af[i][1] = as[(r + 8) * AST + kk + tg];
                af[i][2] = as[r * AST + kk + tg + 4];
                af[i][3] = as[(r + 8) * AST + kk + tg + 4];
            }
            #pragma unroll
            for (int j = 0; j < 4; j++) {
                int c = wn + j * 8 + g;
                bf[j][0] = bs[(kk + tg) * BST + c];
                bf[j][1] = bs[(kk + tg + 4) * BST + c];
            }
            #pragma unroll
            for (int i = 0; i < 4; i++)
                #pragma unroll
                for (int j = 0; j < 4; j++) {
                    asm volatile(
                        "mma.sync.aligned.m16n8k8.row.col.f32.tf32.tf32.f32 "
                        "{%0,%1,%2,%3}, {%4,%5,%6,%7}, {%8,%9}, {%0,%1,%2,%3};"
                        : "+f"(acc[i][j][0]), "+f"(acc[i][j][1]),
                          "+f"(acc[i][j][2]), "+f"(acc[i][j][3])
                        : "r"(af[i][0]), "r"(af[i][1]), "r"(af[i][2]), "r"(af[i][3]),
                          "r"(bf[j][0]), "r"(bf[j][1]));
                }
        }
        if (++buf >= 3) buf = 0;
    }
#undef ISSUE_STAGE

    // epilogue; relu=1 also tf32-rounds the store (FC1 output feeds FC2's A)
    int gm0 = blockIdx.y * 128 + wm;
    int gn0 = blockIdx.x * 128 + wn;
    #pragma unroll
    for (int i = 0; i < 4; i++) {
        #pragma unroll
        for (int j = 0; j < 4; j++) {
            int row = gm0 + i * 16 + g;
            int col = gn0 + j * 8 + tg * 2;
            float b0 = 0.f, b1 = 0.f;
            if (bias) { b0 = bias[col]; b1 = bias[col + 1]; }
            #pragma unroll
            for (int half = 0; half < 2; half++) {
                int r = row + half * 8;
                size_t off = (size_t)r * N + col;
                float v0 = acc[i][j][half * 2 + 0] + b0;
                float v1 = acc[i][j][half * 2 + 1] + b1;
                if (relu) {
                    v0 = f2tf_f(fmaxf(v0, 0.f));
                    v1 = f2tf_f(fmaxf(v1, 0.f));
                }
                if (res)  { v0 += res[off]; v1 += res[off + 1]; }
                *(float2*)(Cm + off) = make_float2(v0, v1);
            }
        }
    }
}

// ---------------- fused flash attention (fp32), tf32-rounded output ----------
__global__ __launch_bounds__(256) void flash_kernel(const float* __restrict__ qkv,
                                                    float* __restrict__ att) {
    int tt = blockIdx.x, z = blockIdx.z;
    int b = z / HN, h = z % HN;
    int t0 = tt * 64;
    __shared__ float qs[64][65];
    __shared__ float ks[32][65];
    __shared__ float vs[32][65];
    __shared__ float ps[64][33];
    int tid = threadIdx.x;
    int g = tid >> 4;           // 0..15 row group
    int c = tid & 15;           // 0..15
    int trow = g * 4;
    const float scale = rsqrtf((float)CN);

    for (int i = tid; i < 64 * 64; i += 256) {
        int r = i >> 6, d = i & 63;
        qs[r][d] = qkv[((size_t)(b * TN + t0 + r)) * QKVN + h * DN + d];
    }

    float m[4], l[4], acc[4][4];
    #pragma unroll
    for (int i = 0; i < 4; i++) {
        m[i] = -1e30f; l[i] = 0.f;
        #pragma unroll
        for (int j = 0; j < 4; j++) acc[i][j] = 0.f;
    }

    int nS = (t0 + 64) / 32;
    for (int st = 0; st < nS; st++) {
        int s0 = st * 32;
        __syncthreads();
        for (int i = tid; i < 32 * 64; i += 256) {
            int r = i >> 6, d = i & 63;
            size_t base = ((size_t)(b * TN + s0 + r)) * QKVN + h * DN + d;
            ks[r][d] = qkv[base + CN];
            vs[r][d] = qkv[base + 2 * CN];
        }
        __syncthreads();

        float s[4][2];
        #pragma unroll
        for (int i = 0; i < 4; i++) { s[i][0] = 0.f; s[i][1] = 0.f; }
        #pragma unroll 8
        for (int d = 0; d < 64; d++) {
            float k0 = ks[c * 2][d], k1 = ks[c * 2 + 1][d];
            #pragma unroll
            for (int i = 0; i < 4; i++) {
                float qv = qs[trow + i][d];
                s[i][0] = fmaf(qv, k0, s[i][0]);
                s[i][1] = fmaf(qv, k1, s[i][1]);
            }
        }
        #pragma unroll
        for (int i = 0; i < 4; i++) {
            int srow = t0 + trow + i;
            #pragma unroll
            for (int j = 0; j < 2; j++) {
                int scol = s0 + c * 2 + j;
                s[i][j] = (scol <= srow) ? s[i][j] * scale : -1e30f;
            }
        }

        float fac[4];
        #pragma unroll
        for (int i = 0; i < 4; i++) {
            float tm = fmaxf(s[i][0], s[i][1]);
            #pragma unroll
            for (int o = 1; o < 16; o <<= 1)
                tm = fmaxf(tm, __shfl_xor_sync(0xffffffffu, tm, o));
            float mn = fmaxf(m[i], tm);
            fac[i] = __expf(m[i] - mn);
            m[i] = mn;
            float p0 = __expf(s[i][0] - mn);
            float p1 = __expf(s[i][1] - mn);
            ps[trow + i][c * 2 + 0] = p0;
            ps[trow + i][c * 2 + 1] = p1;
            float rs = p0 + p1;
            #pragma unroll
            for (int o = 1; o < 16; o <<= 1)
                rs += __shfl_xor_sync(0xffffffffu, rs, o);
            l[i] = l[i] * fac[i] + rs;
        }
        #pragma unroll
        for (int i = 0; i < 4; i++)
            #pragma unroll
            for (int j = 0; j < 4; j++) acc[i][j] *= fac[i];
        __syncthreads();

        #pragma unroll 8
        for (int ss = 0; ss < 32; ss++) {
            float pv0 = ps[trow + 0][ss], pv1 = ps[trow + 1][ss];
            float pv2 = ps[trow + 2][ss], pv3 = ps[trow + 3][ss];
            #pragma unroll
            for (int j = 0; j < 4; j++) {
                float vv = vs[ss][c * 4 + j];
                acc[0][j] = fmaf(pv0, vv, acc[0][j]);
                acc[1][j] = fmaf(pv1, vv, acc[1][j]);
                acc[2][j] = fmaf(pv2, vv, acc[2][j]);
                acc[3][j] = fmaf(pv3, vv, acc[3][j]);
            }
        }
    }

    #pragma unroll
    for (int i = 0; i < 4; i++) {
        float inv = 1.f / l[i];
        float4 o4 = make_float4(f2tf_f(acc[i][0] * inv), f2tf_f(acc[i][1] * inv),
                                f2tf_f(acc[i][2] * inv), f2tf_f(acc[i][3] * inv));
        *(float4*)(att + ((size_t)(b * TN + t0 + trow + i)) * CN + h * DN + c * 4) = o4;
    }
}

// ---------------- host orchestration ----------------------------------------
extern "C" void kernel_launch(void* const* d_in, const int* in_sizes, int n_in,
                              void* d_out, int out_size) {
    const int*   x       = (const int*)  d_in[0];
    const float* tok_emb = (const float*)d_in[1];
    const float* pos_emb = (const float*)d_in[2];
    const float* Wq      = (const float*)d_in[3];
    const float* Wk      = (const float*)d_in[4];
    const float* Wv      = (const float*)d_in[5];
    const float* Wo      = (const float*)d_in[6];
    const float* bo      = (const float*)d_in[7];
    const float* ln1_g   = (const float*)d_in[8];
    const float* ln1_b   = (const float*)d_in[9];
    const float* ln2_g   = (const float*)d_in[10];
    const float* ln2_b   = (const float*)d_in[11];
    const float* W1      = (const float*)d_in[12];
    const float* b1      = (const float*)d_in[13];
    const float* W2      = (const float*)d_in[14];
    const float* b2      = (const float*)d_in[15];
    const float* lnf_g   = (const float*)d_in[16];
    const float* lnf_b   = (const float*)d_in[17];
    const float* Wh      = (const float*)d_in[18];
    const float* bh      = (const float*)d_in[19];
    float* out = (float*)d_out;

    float *ph, *pain, *pqkv, *patt, *pffn, *pwt, *pwoc, *pw1c, *pw2c, *pwhc;
    cudaGetSymbolAddress((void**)&ph,   g_h);
    cudaGetSymbolAddress((void**)&pain, g_ain);
    cudaGetSymbolAddress((void**)&pqkv, g_qkv);
    cudaGetSymbolAddress((void**)&patt, g_att);
    cudaGetSymbolAddress((void**)&pffn, g_ffn);
    cudaGetSymbolAddress((void**)&pwt,  g_wt);
    cudaGetSymbolAddress((void**)&pwoc, g_woc);
    cudaGetSymbolAddress((void**)&pw1c, g_w1c);
    cudaGetSymbolAddress((void**)&pw2c, g_w2c);
    cudaGetSymbolAddress((void**)&pwhc, g_whc);

    cudaFuncSetAttribute(tgemm_kernel,
                         cudaFuncAttributeMaxDynamicSharedMemorySize, TG_SMEM);

    const int HCD = HN * CN * DN;

    // one-time per-call tf32 weight conversions
    {
        int n4;
        n4 = CN * VN / 4;
        cvtf_kernel<<<(n4 + 255) / 256, 256>>>((const float4*)Wh, (float4*)pwhc, n4);
        n4 = LN * CN * CN / 4;
        cvtf_kernel<<<(n4 + 255) / 256, 256>>>((const float4*)Wo, (float4*)pwoc, n4);
        n4 = LN * CN * FN / 4;
        cvtf_kernel<<<(n4 + 255) / 256, 256>>>((const float4*)W1, (float4*)pw1c, n4);
        n4 = LN * FN * CN / 4;
        cvtf_kernel<<<(n4 + 255) / 256, 256>>>((const float4*)W2, (float4*)pw2c, n4);
    }

    embed_kernel<<<(BT * CN + 255) / 256, 256>>>(x, tok_emb, pos_emb, ph);

    for (int l = 0; l < LN; l++) {
        layernorm_kernel<<<BT, 256>>>(ph, ln1_g + l * CN, ln1_b + l * CN, pain);
        transpose_qkv_kernel<<<(3 * HCD + 255) / 256, 256>>>(
            Wq + (size_t)l * HCD, Wk + (size_t)l * HCD, Wv + (size_t)l * HCD, pwt);
        tgemm_kernel<<<dim3(QKVN / 128, BT / 128), 256, TG_SMEM>>>(
            pain, pwt, pqkv, nullptr, nullptr, BT, QKVN, CN, 0);
        flash_kernel<<<dim3(TN / 64, 1, BN_ * HN), 256>>>(pqkv, patt);
        tgemm_kernel<<<dim3(CN / 128, BT / 128), 256, TG_SMEM>>>(
            patt, pwoc + (size_t)l * CN * CN, ph, bo + l * CN, ph, BT, CN, CN, 0);
        layernorm_kernel<<<BT, 256>>>(ph, ln2_g + l * CN, ln2_b + l * CN, pain);
        tgemm_kernel<<<dim3(FN / 128, BT / 128), 256, TG_SMEM>>>(
            pain, pw1c + (size_t)l * CN * FN, pffn, b1 + l * FN, nullptr, BT, FN, CN, 1);
        tgemm_kernel<<<dim3(CN / 128, BT / 128), 256, TG_SMEM>>>(
            pffn, pw2c + (size_t)l * FN * CN, ph, b2 + l * CN, ph, BT, CN, FN, 0);
    }

    layernorm_kernel<<<BT, 256>>>(ph, lnf_g, lnf_b, pain);
    tgemm_kernel<<<dim3(VN / 128, BT / 128), 256, TG_SMEM>>>(
        pain, pwhc, out, bh, nullptr, BT, VN, CN, 0);
}